// round 5
// baseline (speedup 1.0000x reference)
#include <cuda_runtime.h>
#include <cuda_bf16.h>
#include <cstdint>

#define N_NODES 50000
#define N_EDGES 800000
#define D 128

// ---------------------------------------------------------------------------
// Scratch (device globals: allocation-free per harness rules)
// ---------------------------------------------------------------------------
__device__ float4 g_hn4[(size_t)N_NODES * D / 4];  // h_neigh (mean), 25.6MB
__device__ int    g_cnt[N_NODES];                  // in-degree
__device__ int    g_off[N_NODES];                  // CSR offsets (exclusive scan)
__device__ int    g_cur[N_NODES];                  // fill cursors
__device__ int    g_esrc[N_EDGES];                 // src node per edge, bucketed by dst
__device__ int    g_stride;                        // 1 = indices are int32, 2 = int64

// ---------------------------------------------------------------------------
// K-1: probe index dtype. If indices are int64 (values < 2^31), every odd
// 32-bit word is 0. If int32, odd words are random node ids — all-zero over
// 512 samples is impossible. Deterministic, graph-capturable.
// ---------------------------------------------------------------------------
__global__ void probe_kernel(const int* __restrict__ dst_w) {
    __shared__ int any_nonzero;
    if (threadIdx.x == 0) any_nonzero = 0;
    __syncthreads();
    int i = 1 + 2 * threadIdx.x;          // odd words 1..1023 (256 threads x2)
    int v0 = dst_w[i];
    int v1 = dst_w[i + 512];
    if ((v0 | v1) != 0) atomicOr(&any_nonzero, 1);
    __syncthreads();
    if (threadIdx.x == 0) g_stride = any_nonzero ? 1 : 2;
}

// ---------------------------------------------------------------------------
// K0: zero counters
// ---------------------------------------------------------------------------
__global__ void zero_kernel() {
    int i = blockIdx.x * blockDim.x + threadIdx.x;
    if (i < N_NODES) { g_cnt[i] = 0; g_cur[i] = 0; }
}

// ---------------------------------------------------------------------------
// K1: degree histogram (int atomics only)
// ---------------------------------------------------------------------------
__global__ void count_kernel(const int* __restrict__ dst_w) {
    int e = blockIdx.x * blockDim.x + threadIdx.x;
    if (e >= N_EDGES) return;
    int d = dst_w[(size_t)e * g_stride];
    atomicAdd(&g_cnt[d], 1);
}

// ---------------------------------------------------------------------------
// K2: exclusive scan over 50K counts, single block of 1024 threads.
// ---------------------------------------------------------------------------
__global__ void scan_kernel() {
    __shared__ int part[1024];
    const int T = 1024;
    const int chunk = (N_NODES + T - 1) / T;  // 49
    int t = threadIdx.x;
    int lo = t * chunk;
    int hi = lo + chunk < N_NODES ? lo + chunk : N_NODES;

    int s = 0;
    for (int i = lo; i < hi; i++) s += g_cnt[i];
    part[t] = s;
    __syncthreads();

    for (int off = 1; off < T; off <<= 1) {
        int v = (t >= off) ? part[t - off] : 0;
        __syncthreads();
        part[t] += v;
        __syncthreads();
    }

    int run = (t > 0) ? part[t - 1] : 0;  // exclusive prefix of this chunk
    for (int i = lo; i < hi; i++) { g_off[i] = run; run += g_cnt[i]; }
}

// ---------------------------------------------------------------------------
// K3: bucket fill — place each edge's src into its dst's CSR slot
// ---------------------------------------------------------------------------
__global__ void fill_kernel(const int* __restrict__ src_w,
                            const int* __restrict__ dst_w) {
    int e = blockIdx.x * blockDim.x + threadIdx.x;
    if (e >= N_EDGES) return;
    int st = g_stride;
    int d = dst_w[(size_t)e * st];
    int s = src_w[(size_t)e * st];
    int pos = atomicAdd(&g_cur[d], 1);
    g_esrc[g_off[d] + pos] = s;
}

// ---------------------------------------------------------------------------
// K4: aggregate — one warp per node, register accumulation, zero FP atomics.
// Lane l owns float4 chunk l of the 128-dim row. x4 unroll for MLP vs L2 lat.
// ---------------------------------------------------------------------------
__global__ void aggregate_kernel(const float* __restrict__ feat) {
    int warp = (blockIdx.x * blockDim.x + threadIdx.x) >> 5;
    int lane = threadIdx.x & 31;
    if (warp >= N_NODES) return;

    int start = g_off[warp];
    int cnt   = g_cnt[warp];
    int end   = start + cnt;

    float4 acc = make_float4(0.f, 0.f, 0.f, 0.f);
    int e = start;
    for (; e + 4 <= end; e += 4) {
        int s0 = g_esrc[e + 0];   // same addr across warp -> broadcast
        int s1 = g_esrc[e + 1];
        int s2 = g_esrc[e + 2];
        int s3 = g_esrc[e + 3];
        float4 v0 = ((const float4*)(feat + (size_t)s0 * D))[lane];
        float4 v1 = ((const float4*)(feat + (size_t)s1 * D))[lane];
        float4 v2 = ((const float4*)(feat + (size_t)s2 * D))[lane];
        float4 v3 = ((const float4*)(feat + (size_t)s3 * D))[lane];
        acc.x += (v0.x + v1.x) + (v2.x + v3.x);
        acc.y += (v0.y + v1.y) + (v2.y + v3.y);
        acc.z += (v0.z + v1.z) + (v2.z + v3.z);
        acc.w += (v0.w + v1.w) + (v2.w + v3.w);
    }
    for (; e < end; e++) {
        int s0 = g_esrc[e];
        float4 v0 = ((const float4*)(feat + (size_t)s0 * D))[lane];
        acc.x += v0.x; acc.y += v0.y; acc.z += v0.z; acc.w += v0.w;
    }

    float inv = 1.0f / (float)(cnt > 1 ? cnt : 1);
    acc.x *= inv; acc.y *= inv; acc.z *= inv; acc.w *= inv;
    g_hn4[(size_t)warp * (D / 4) + lane] = acc;
}

// ---------------------------------------------------------------------------
// K5: fused dual GEMM + bias: out = feat@Ws + h_neigh@Wn + b
// 256 threads, TM=64 nodes x 128 cols, KC=32 k-chunks. 48KB smem.
// ---------------------------------------------------------------------------
#define TM 64
#define KC 32

__global__ __launch_bounds__(256, 4)
void gemm_kernel(const float* __restrict__ feat,
                 const float* __restrict__ Ws,
                 const float* __restrict__ Wn,
                 const float* __restrict__ bias,
                 float* __restrict__ out) {
    extern __shared__ float sm[];
    float* Ws_s = sm;                      // [KC][D]
    float* Wn_s = Ws_s + KC * D;           // [KC][D]
    float* fe_s = Wn_s + KC * D;           // [TM][KC]
    float* hn_s = fe_s + TM * KC;          // [TM][KC]

    const int tid = threadIdx.x;
    const int tx = tid & 31;               // column group (4 cols each)
    const int ty = tid >> 5;               // node group (8 nodes each)
    const int node0 = blockIdx.x * TM;
    const float* hng = (const float*)g_hn4;

    float4 bv = ((const float4*)bias)[tx];
    float acc[8][4];
#pragma unroll
    for (int i = 0; i < 8; i++) {
        acc[i][0] = bv.x; acc[i][1] = bv.y; acc[i][2] = bv.z; acc[i][3] = bv.w;
    }

    for (int kc = 0; kc < D; kc += KC) {
        {
            const float4* wsg = (const float4*)(Ws + (size_t)kc * D);
            const float4* wng = (const float4*)(Wn + (size_t)kc * D);
            float4* wss = (float4*)Ws_s;
            float4* wns = (float4*)Wn_s;
#pragma unroll
            for (int i = tid; i < KC * D / 4; i += 256) {
                wss[i] = wsg[i];
                wns[i] = wng[i];
            }
        }
#pragma unroll
        for (int i = tid; i < TM * KC / 4; i += 256) {
            int n  = i / (KC / 4);
            int c4 = i % (KC / 4);
            int gn = node0 + n;
            float4 fv = make_float4(0.f, 0.f, 0.f, 0.f);
            float4 sv = make_float4(0.f, 0.f, 0.f, 0.f);
            if (gn < N_NODES) {
                fv = ((const float4*)(feat + (size_t)gn * D + kc))[c4];
                sv = ((const float4*)(hng  + (size_t)gn * D + kc))[c4];
            }
            ((float4*)(fe_s + n * KC))[c4] = fv;
            ((float4*)(hn_s + n * KC))[c4] = sv;
        }
        __syncthreads();

#pragma unroll
        for (int k = 0; k < KC; k++) {
            float4 ws = ((const float4*)(Ws_s + k * D))[tx];
            float4 wn = ((const float4*)(Wn_s + k * D))[tx];
#pragma unroll
            for (int i = 0; i < 8; i++) {
                float f = fe_s[(ty * 8 + i) * KC + k];
                float h = hn_s[(ty * 8 + i) * KC + k];
                acc[i][0] = fmaf(f, ws.x, fmaf(h, wn.x, acc[i][0]));
                acc[i][1] = fmaf(f, ws.y, fmaf(h, wn.y, acc[i][1]));
                acc[i][2] = fmaf(f, ws.z, fmaf(h, wn.z, acc[i][2]));
                acc[i][3] = fmaf(f, ws.w, fmaf(h, wn.w, acc[i][3]));
            }
        }
        __syncthreads();
    }

#pragma unroll
    for (int i = 0; i < 8; i++) {
        int gn = node0 + ty * 8 + i;
        if (gn < N_NODES) {
            float4 o;
            o.x = acc[i][0]; o.y = acc[i][1]; o.z = acc[i][2]; o.w = acc[i][3];
            ((float4*)(out + (size_t)gn * D))[tx] = o;
        }
    }
}

// ---------------------------------------------------------------------------
// Launch
// ---------------------------------------------------------------------------
extern "C" void kernel_launch(void* const* d_in, const int* in_sizes, int n_in,
                              void* d_out, int out_size) {
    const float* feat  = (const float*)d_in[0];
    const int*   src_w = (const int*)d_in[1];   // int32 words (or int64 lo/hi pairs)
    const int*   dst_w = (const int*)d_in[2];
    const float* Ws    = (const float*)d_in[3];
    const float* Wn    = (const float*)d_in[4];
    const float* b     = (const float*)d_in[5];
    float*       out   = (float*)d_out;

    probe_kernel<<<1, 256>>>(dst_w);
    zero_kernel<<<(N_NODES + 255) / 256, 256>>>();
    count_kernel<<<(N_EDGES + 255) / 256, 256>>>(dst_w);
    scan_kernel<<<1, 1024>>>();
    fill_kernel<<<(N_EDGES + 255) / 256, 256>>>(src_w, dst_w);

    {   // aggregate: one warp per node, 8 warps per block
        int threads = 256;
        int blocks = (N_NODES * 32 + threads - 1) / threads;
        aggregate_kernel<<<blocks, threads>>>(feat);
    }

    {   // fused dual GEMM + bias
        int threads = 256;
        int blocks = (N_NODES + TM - 1) / TM;
        size_t smem = (size_t)(2 * KC * D + 2 * TM * KC) * sizeof(float); // 48KB
        gemm_kernel<<<blocks, threads, smem>>>(feat, Ws, Wn, b, out);
    }
}

// round 6
// speedup vs baseline: 2.3740x; 2.3740x over previous
#include <cuda_runtime.h>
#include <cuda_bf16.h>
#include <cstdint>

#define N_NODES 50000
#define N_EDGES 800000
#define D 128

typedef unsigned long long u64;

// ---------------------------------------------------------------------------
// Scratch (device globals: allocation-free per harness rules)
// ---------------------------------------------------------------------------
__device__ float4 g_hn4[(size_t)N_NODES * D / 4];  // h_neigh (mean), 25.6MB
__device__ int    g_cnt[N_NODES];                  // in-degree
__device__ int    g_off[N_NODES];                  // CSR offsets (exclusive scan)
__device__ int    g_cur[N_NODES];                  // fill cursors
__device__ int    g_esrc[N_EDGES];                 // src per edge, bucketed by dst
__device__ int    g_bsum[64];                      // scan block sums
__device__ int    g_stride;                        // 1 = int32 indices, 2 = int64

// ---------------------------------------------------------------------------
// packed f32x2 helpers (FFMA2 only reachable via PTX)
// ---------------------------------------------------------------------------
__device__ __forceinline__ u64 pack2(float lo, float hi) {
    u64 r; asm("mov.b64 %0, {%1, %2};" : "=l"(r) : "f"(lo), "f"(hi)); return r;
}
__device__ __forceinline__ void fma2(u64& d, u64 a, u64 b) {
    asm("fma.rn.f32x2 %0, %1, %2, %0;" : "+l"(d) : "l"(a), "l"(b));
}
__device__ __forceinline__ float2 unpack2(u64 v) {
    float2 f; asm("mov.b64 {%0, %1}, %2;" : "=f"(f.x), "=f"(f.y) : "l"(v)); return f;
}

// ---------------------------------------------------------------------------
// K-1: probe index dtype (odd 32-bit words all zero <=> int64 little-endian)
// ---------------------------------------------------------------------------
__global__ void probe_kernel(const int* __restrict__ dst_w) {
    __shared__ int any_nonzero;
    if (threadIdx.x == 0) any_nonzero = 0;
    __syncthreads();
    int i = 1 + 2 * threadIdx.x;
    int v0 = dst_w[i];
    int v1 = dst_w[i + 512];
    if ((v0 | v1) != 0) atomicOr(&any_nonzero, 1);
    __syncthreads();
    if (threadIdx.x == 0) g_stride = any_nonzero ? 1 : 2;
}

// ---------------------------------------------------------------------------
// K0: zero counters
// ---------------------------------------------------------------------------
__global__ void zero_kernel() {
    int i = blockIdx.x * blockDim.x + threadIdx.x;
    if (i < N_NODES) { g_cnt[i] = 0; g_cur[i] = 0; }
}

// ---------------------------------------------------------------------------
// K1: degree histogram (int atomics only)
// ---------------------------------------------------------------------------
__global__ void count_kernel(const int* __restrict__ dst_w) {
    int e = blockIdx.x * blockDim.x + threadIdx.x;
    if (e >= N_EDGES) return;
    atomicAdd(&g_cnt[dst_w[(size_t)e * g_stride]], 1);
}

// ---------------------------------------------------------------------------
// K2a/b/c: parallel exclusive scan (replaces the 47.6us single-CTA scan)
// ---------------------------------------------------------------------------
#define SCAN_CHUNK 1024
#define SCAN_BLOCKS ((N_NODES + SCAN_CHUNK - 1) / SCAN_CHUNK)  // 49

__global__ void scan1_kernel() {               // per-block totals
    __shared__ int ssum[256];
    int b = blockIdx.x, t = threadIdx.x;
    int base = b * SCAN_CHUNK;
    int s = 0;
#pragma unroll
    for (int i = t; i < SCAN_CHUNK; i += 256) {
        int idx = base + i;
        if (idx < N_NODES) s += g_cnt[idx];
    }
    ssum[t] = s;
    __syncthreads();
    for (int o = 128; o > 0; o >>= 1) {
        if (t < o) ssum[t] += ssum[t + o];
        __syncthreads();
    }
    if (t == 0) g_bsum[b] = ssum[0];
}

__global__ void scan2_kernel() {               // exclusive scan of 49 sums
    if (threadIdx.x == 0) {
        int run = 0;
#pragma unroll
        for (int i = 0; i < SCAN_BLOCKS; i++) {
            int v = g_bsum[i];
            g_bsum[i] = run;
            run += v;
        }
    }
}

__global__ void scan3_kernel() {               // per-block exclusive scan + base
    __shared__ int tsum[256];
    int b = blockIdx.x, t = threadIdx.x;
    int idx0 = b * SCAN_CHUNK + t * 4;
    int v[4], s = 0;
#pragma unroll
    for (int j = 0; j < 4; j++) {
        int idx = idx0 + j;
        v[j] = (idx < N_NODES) ? g_cnt[idx] : 0;
        s += v[j];
    }
    tsum[t] = s;
    __syncthreads();
    for (int o = 1; o < 256; o <<= 1) {
        int x = (t >= o) ? tsum[t - o] : 0;
        __syncthreads();
        tsum[t] += x;
        __syncthreads();
    }
    int run = g_bsum[b] + (t > 0 ? tsum[t - 1] : 0);
#pragma unroll
    for (int j = 0; j < 4; j++) {
        int idx = idx0 + j;
        if (idx < N_NODES) g_off[idx] = run;
        run += v[j];
    }
}

// ---------------------------------------------------------------------------
// K3: bucket fill
// ---------------------------------------------------------------------------
__global__ void fill_kernel(const int* __restrict__ src_w,
                            const int* __restrict__ dst_w) {
    int e = blockIdx.x * blockDim.x + threadIdx.x;
    if (e >= N_EDGES) return;
    int st = g_stride;
    int d = dst_w[(size_t)e * st];
    int s = src_w[(size_t)e * st];
    int pos = atomicAdd(&g_cur[d], 1);
    g_esrc[g_off[d] + pos] = s;
}

// ---------------------------------------------------------------------------
// K4: aggregate — one warp per node, register accumulation
// ---------------------------------------------------------------------------
__global__ void aggregate_kernel(const float* __restrict__ feat) {
    int warp = (blockIdx.x * blockDim.x + threadIdx.x) >> 5;
    int lane = threadIdx.x & 31;
    if (warp >= N_NODES) return;

    int start = g_off[warp];
    int cnt   = g_cnt[warp];
    int end   = start + cnt;

    float4 acc = make_float4(0.f, 0.f, 0.f, 0.f);
    int e = start;
    for (; e + 4 <= end; e += 4) {
        int s0 = g_esrc[e + 0];
        int s1 = g_esrc[e + 1];
        int s2 = g_esrc[e + 2];
        int s3 = g_esrc[e + 3];
        float4 v0 = ((const float4*)(feat + (size_t)s0 * D))[lane];
        float4 v1 = ((const float4*)(feat + (size_t)s1 * D))[lane];
        float4 v2 = ((const float4*)(feat + (size_t)s2 * D))[lane];
        float4 v3 = ((const float4*)(feat + (size_t)s3 * D))[lane];
        acc.x += (v0.x + v1.x) + (v2.x + v3.x);
        acc.y += (v0.y + v1.y) + (v2.y + v3.y);
        acc.z += (v0.z + v1.z) + (v2.z + v3.z);
        acc.w += (v0.w + v1.w) + (v2.w + v3.w);
    }
    for (; e < end; e++) {
        int s0 = g_esrc[e];
        float4 v0 = ((const float4*)(feat + (size_t)s0 * D))[lane];
        acc.x += v0.x; acc.y += v0.y; acc.z += v0.z; acc.w += v0.w;
    }

    float inv = 1.0f / (float)(cnt > 1 ? cnt : 1);
    acc.x *= inv; acc.y *= inv; acc.z *= inv; acc.w *= inv;
    g_hn4[(size_t)warp * (D / 4) + lane] = acc;
}

// ---------------------------------------------------------------------------
// K5: fused dual GEMM + bias with packed f32x2 FMA:
//   out = feat @ W_self + h_neigh @ W_neigh + b
// 256 thr, TM=64 x 128 cols, KC=32. 48KB smem. k unrolled x4 so A-tile
// broadcasts use LDS128 (keeps LDS pipe under the halved fma-pipe bound).
// ---------------------------------------------------------------------------
#define TM 64
#define KC 32

__global__ __launch_bounds__(256, 2)
void gemm_kernel(const float* __restrict__ feat,
                 const float* __restrict__ Ws,
                 const float* __restrict__ Wn,
                 const float* __restrict__ bias,
                 float* __restrict__ out) {
    extern __shared__ float sm[];
    float* Ws_s = sm;                      // [KC][D]
    float* Wn_s = Ws_s + KC * D;           // [KC][D]
    float* fe_s = Wn_s + KC * D;           // [TM][KC]
    float* hn_s = fe_s + TM * KC;          // [TM][KC]

    const int tid = threadIdx.x;
    const int tx = tid & 31;               // 4 cols each
    const int ty = tid >> 5;               // 8 rows each
    const int node0 = blockIdx.x * TM;
    const float* hng = (const float*)g_hn4;

    float4 bv = ((const float4*)bias)[tx];
    u64 acc[8][2];
#pragma unroll
    for (int i = 0; i < 8; i++) {
        acc[i][0] = pack2(bv.x, bv.y);
        acc[i][1] = pack2(bv.z, bv.w);
    }

    for (int kc = 0; kc < D; kc += KC) {
        {
            const float4* wsg = (const float4*)(Ws + (size_t)kc * D);
            const float4* wng = (const float4*)(Wn + (size_t)kc * D);
            float4* wss = (float4*)Ws_s;
            float4* wns = (float4*)Wn_s;
#pragma unroll
            for (int i = tid; i < KC * D / 4; i += 256) {
                wss[i] = wsg[i];
                wns[i] = wng[i];
            }
        }
#pragma unroll
        for (int i = tid; i < TM * KC / 4; i += 256) {
            int n  = i / (KC / 4);
            int c4 = i % (KC / 4);
            int gn = node0 + n;
            float4 fv = make_float4(0.f, 0.f, 0.f, 0.f);
            float4 sv = make_float4(0.f, 0.f, 0.f, 0.f);
            if (gn < N_NODES) {
                fv = ((const float4*)(feat + (size_t)gn * D + kc))[c4];
                sv = ((const float4*)(hng  + (size_t)gn * D + kc))[c4];
            }
            ((float4*)(fe_s + n * KC))[c4] = fv;
            ((float4*)(hn_s + n * KC))[c4] = sv;
        }
        __syncthreads();

#pragma unroll
        for (int k4 = 0; k4 < KC; k4 += 4) {
            u64 wsp[4][2], wnp[4][2];
#pragma unroll
            for (int j = 0; j < 4; j++) {
                float4 ws = ((const float4*)(Ws_s + (k4 + j) * D))[tx];
                float4 wn = ((const float4*)(Wn_s + (k4 + j) * D))[tx];
                wsp[j][0] = pack2(ws.x, ws.y); wsp[j][1] = pack2(ws.z, ws.w);
                wnp[j][0] = pack2(wn.x, wn.y); wnp[j][1] = pack2(wn.z, wn.w);
            }
#pragma unroll
            for (int i = 0; i < 8; i++) {
                const int row = ty * 8 + i;
                float4 f4 = *(const float4*)(fe_s + row * KC + k4);  // broadcast
                float4 h4 = *(const float4*)(hn_s + row * KC + k4);
                u64 ff, hh;
                ff = pack2(f4.x, f4.x); hh = pack2(h4.x, h4.x);
                fma2(acc[i][0], ff, wsp[0][0]); fma2(acc[i][1], ff, wsp[0][1]);
                fma2(acc[i][0], hh, wnp[0][0]); fma2(acc[i][1], hh, wnp[0][1]);
                ff = pack2(f4.y, f4.y); hh = pack2(h4.y, h4.y);
                fma2(acc[i][0], ff, wsp[1][0]); fma2(acc[i][1], ff, wsp[1][1]);
                fma2(acc[i][0], hh, wnp[1][0]); fma2(acc[i][1], hh, wnp[1][1]);
                ff = pack2(f4.z, f4.z); hh = pack2(h4.z, h4.z);
                fma2(acc[i][0], ff, wsp[2][0]); fma2(acc[i][1], ff, wsp[2][1]);
                fma2(acc[i][0], hh, wnp[2][0]); fma2(acc[i][1], hh, wnp[2][1]);
                ff = pack2(f4.w, f4.w); hh = pack2(h4.w, h4.w);
                fma2(acc[i][0], ff, wsp[3][0]); fma2(acc[i][1], ff, wsp[3][1]);
                fma2(acc[i][0], hh, wnp[3][0]); fma2(acc[i][1], hh, wnp[3][1]);
            }
        }
        __syncthreads();
    }

#pragma unroll
    for (int i = 0; i < 8; i++) {
        int gn = node0 + ty * 8 + i;
        if (gn < N_NODES) {
            float2 lo = unpack2(acc[i][0]);
            float2 hi = unpack2(acc[i][1]);
            float4 o;
            o.x = lo.x; o.y = lo.y; o.z = hi.x; o.w = hi.y;
            ((float4*)(out + (size_t)gn * D))[tx] = o;
        }
    }
}

// ---------------------------------------------------------------------------
// Launch
// ---------------------------------------------------------------------------
extern "C" void kernel_launch(void* const* d_in, const int* in_sizes, int n_in,
                              void* d_out, int out_size) {
    const float* feat  = (const float*)d_in[0];
    const int*   src_w = (const int*)d_in[1];
    const int*   dst_w = (const int*)d_in[2];
    const float* Ws    = (const float*)d_in[3];
    const float* Wn    = (const float*)d_in[4];
    const float* b     = (const float*)d_in[5];
    float*       out   = (float*)d_out;

    probe_kernel<<<1, 256>>>(dst_w);
    zero_kernel<<<(N_NODES + 255) / 256, 256>>>();
    count_kernel<<<(N_EDGES + 255) / 256, 256>>>(dst_w);
    scan1_kernel<<<SCAN_BLOCKS, 256>>>();
    scan2_kernel<<<1, 32>>>();
    scan3_kernel<<<SCAN_BLOCKS, 256>>>();
    fill_kernel<<<(N_EDGES + 255) / 256, 256>>>(src_w, dst_w);

    {   // aggregate: one warp per node
        int threads = 256;
        int blocks = (N_NODES * 32 + threads - 1) / threads;
        aggregate_kernel<<<blocks, threads>>>(feat);
    }

    {   // fused dual GEMM + bias (packed f32x2)
        int threads = 256;
        int blocks = (N_NODES + TM - 1) / TM;
        size_t smem = (size_t)(2 * KC * D + 2 * TM * KC) * sizeof(float); // 48KB
        gemm_kernel<<<blocks, threads, smem>>>(feat, Ws, Wn, b, out);
    }
}

// round 7
// speedup vs baseline: 3.4350x; 1.4469x over previous
#include <cuda_runtime.h>
#include <cuda_bf16.h>
#include <cstdint>

#define N_NODES 50000
#define N_EDGES 800000
#define D 128

typedef unsigned int u32;

// ---------------------------------------------------------------------------
// Scratch (device globals: allocation-free per harness rules)
// ---------------------------------------------------------------------------
__device__ float4 g_hn4[(size_t)N_NODES * D / 4];  // h_neigh (mean), 25.6MB
__device__ int    g_cnt[N_NODES];                  // in-degree
__device__ int    g_off[N_NODES];                  // CSR offsets (exclusive scan)
__device__ int    g_cur[N_NODES];                  // fill cursors
__device__ int    g_esrc[N_EDGES];                 // src per edge, bucketed by dst
__device__ int    g_bsum[64];                      // scan block sums
__device__ int    g_stride;                        // 1 = int32 indices, 2 = int64

__device__ __forceinline__ u32 f2tf32(float f) {
    u32 r; asm("cvt.rna.tf32.f32 %0, %1;" : "=r"(r) : "f"(f)); return r;
}

// ---------------------------------------------------------------------------
// K0: zero counters + probe index dtype (block 0).
// int64 little-endian with ids < 2^31 => every odd 32-bit word is 0.
// ---------------------------------------------------------------------------
__global__ void zero_probe_kernel(const int* __restrict__ dst_w) {
    int i = blockIdx.x * blockDim.x + threadIdx.x;
    if (i < N_NODES) { g_cnt[i] = 0; g_cur[i] = 0; }
    if (blockIdx.x == 0) {
        __shared__ int any_nonzero;
        if (threadIdx.x == 0) any_nonzero = 0;
        __syncthreads();
        int j = 1 + 2 * threadIdx.x;
        int v0 = dst_w[j];
        int v1 = dst_w[j + 512];
        if ((v0 | v1) != 0) atomicOr(&any_nonzero, 1);
        __syncthreads();
        if (threadIdx.x == 0) g_stride = any_nonzero ? 1 : 2;
    }
}

// ---------------------------------------------------------------------------
// K1: degree histogram (int atomics only)
// ---------------------------------------------------------------------------
__global__ void count_kernel(const int* __restrict__ dst_w) {
    int e = blockIdx.x * blockDim.x + threadIdx.x;
    if (e >= N_EDGES) return;
    atomicAdd(&g_cnt[dst_w[(size_t)e * g_stride]], 1);
}

// ---------------------------------------------------------------------------
// K2a/b/c: parallel exclusive scan
// ---------------------------------------------------------------------------
#define SCAN_CHUNK 1024
#define SCAN_BLOCKS ((N_NODES + SCAN_CHUNK - 1) / SCAN_CHUNK)  // 49

__global__ void scan1_kernel() {               // per-block totals
    __shared__ int ssum[256];
    int b = blockIdx.x, t = threadIdx.x;
    int base = b * SCAN_CHUNK;
    int s = 0;
#pragma unroll
    for (int i = t; i < SCAN_CHUNK; i += 256) {
        int idx = base + i;
        if (idx < N_NODES) s += g_cnt[idx];
    }
    ssum[t] = s;
    __syncthreads();
    for (int o = 128; o > 0; o >>= 1) {
        if (t < o) ssum[t] += ssum[t + o];
        __syncthreads();
    }
    if (t == 0) g_bsum[b] = ssum[0];
}

__global__ void scan2_kernel() {               // exclusive scan of 49 sums
    if (threadIdx.x == 0) {
        int run = 0;
#pragma unroll
        for (int i = 0; i < SCAN_BLOCKS; i++) {
            int v = g_bsum[i];
            g_bsum[i] = run;
            run += v;
        }
    }
}

__global__ void scan3_kernel() {               // per-block exclusive scan + base
    __shared__ int tsum[256];
    int b = blockIdx.x, t = threadIdx.x;
    int idx0 = b * SCAN_CHUNK + t * 4;
    int v[4], s = 0;
#pragma unroll
    for (int j = 0; j < 4; j++) {
        int idx = idx0 + j;
        v[j] = (idx < N_NODES) ? g_cnt[idx] : 0;
        s += v[j];
    }
    tsum[t] = s;
    __syncthreads();
    for (int o = 1; o < 256; o <<= 1) {
        int x = (t >= o) ? tsum[t - o] : 0;
        __syncthreads();
        tsum[t] += x;
        __syncthreads();
    }
    int run = g_bsum[b] + (t > 0 ? tsum[t - 1] : 0);
#pragma unroll
    for (int j = 0; j < 4; j++) {
        int idx = idx0 + j;
        if (idx < N_NODES) g_off[idx] = run;
        run += v[j];
    }
}

// ---------------------------------------------------------------------------
// K3: bucket fill
// ---------------------------------------------------------------------------
__global__ void fill_kernel(const int* __restrict__ src_w,
                            const int* __restrict__ dst_w) {
    int e = blockIdx.x * blockDim.x + threadIdx.x;
    if (e >= N_EDGES) return;
    int st = g_stride;
    int d = dst_w[(size_t)e * st];
    int s = src_w[(size_t)e * st];
    int pos = atomicAdd(&g_cur[d], 1);
    g_esrc[g_off[d] + pos] = s;
}

// ---------------------------------------------------------------------------
// K4: aggregate — one warp per node, register accumulation (fp32 exact)
// ---------------------------------------------------------------------------
__global__ void aggregate_kernel(const float* __restrict__ feat) {
    int warp = (blockIdx.x * blockDim.x + threadIdx.x) >> 5;
    int lane = threadIdx.x & 31;
    if (warp >= N_NODES) return;

    int start = g_off[warp];
    int cnt   = g_cnt[warp];
    int end   = start + cnt;

    float4 acc = make_float4(0.f, 0.f, 0.f, 0.f);
    int e = start;
    for (; e + 4 <= end; e += 4) {
        int s0 = g_esrc[e + 0];
        int s1 = g_esrc[e + 1];
        int s2 = g_esrc[e + 2];
        int s3 = g_esrc[e + 3];
        float4 v0 = ((const float4*)(feat + (size_t)s0 * D))[lane];
        float4 v1 = ((const float4*)(feat + (size_t)s1 * D))[lane];
        float4 v2 = ((const float4*)(feat + (size_t)s2 * D))[lane];
        float4 v3 = ((const float4*)(feat + (size_t)s3 * D))[lane];
        acc.x += (v0.x + v1.x) + (v2.x + v3.x);
        acc.y += (v0.y + v1.y) + (v2.y + v3.y);
        acc.z += (v0.z + v1.z) + (v2.z + v3.z);
        acc.w += (v0.w + v1.w) + (v2.w + v3.w);
    }
    for (; e < end; e++) {
        int s0 = g_esrc[e];
        float4 v0 = ((const float4*)(feat + (size_t)s0 * D))[lane];
        acc.x += v0.x; acc.y += v0.y; acc.z += v0.z; acc.w += v0.w;
    }

    float inv = 1.0f / (float)(cnt > 1 ? cnt : 1);
    acc.x *= inv; acc.y *= inv; acc.z *= inv; acc.w *= inv;
    g_hn4[(size_t)warp * (D / 4) + lane] = acc;
}

// ---------------------------------------------------------------------------
// K5: fused dual GEMM on tensor cores (tf32 mma.sync.m16n8k8):
//   out = [feat | h_neigh] @ [Ws ; Wn] + b     (virtual K = 256)
// CTA: 256 thr (8 warps, 2x4), tile 128 rows x 128 cols, KC=32 per stage.
// A_s stride 36 / B_s stride 132 -> conflict-free fragment loads.
// h_neigh stays fp32 through aggregation; only GEMM inputs round to tf32
// (predicted rel_err ~4e-4 < 1e-3).
// ---------------------------------------------------------------------------
#define KC 32

__global__ __launch_bounds__(256)
void gemm_tf32_kernel(const float* __restrict__ feat,
                      const float* __restrict__ Ws,
                      const float* __restrict__ Wn,
                      const float* __restrict__ bias,
                      float* __restrict__ out) {
    __shared__ __align__(16) u32 A_s[128][36];
    __shared__ __align__(16) u32 B_s[KC][132];

    const int tid  = threadIdx.x;
    const int wid  = tid >> 5;
    const int lane = tid & 31;
    const int wm   = wid >> 2;      // 0..1 : row half (64 rows)
    const int wn   = wid & 3;       // 0..3 : col quarter (32 cols)
    const int gid  = lane >> 2;     // 0..7
    const int t4   = lane & 3;      // 0..3
    const int node0 = blockIdx.x * 128;
    const float* hng = (const float*)g_hn4;

    float d[4][4][4];
#pragma unroll
    for (int mt = 0; mt < 4; mt++)
#pragma unroll
        for (int nt = 0; nt < 4; nt++)
#pragma unroll
            for (int r = 0; r < 4; r++) d[mt][nt][r] = 0.f;

    for (int kc = 0; kc < 2 * D; kc += KC) {
        // ---- load A tile: 128 rows x 32 k (feat for k<128, h_neigh after) ----
        const float* Asrc = (kc < D) ? (feat + kc) : (hng + (kc - D));
        {
            int r  = tid >> 3;            // 0..31
            int c4 = (tid & 7) * 4;       // 0..28
#pragma unroll
            for (int rr = 0; rr < 128; rr += 32) {
                int gn = node0 + r + rr;
                float4 v = make_float4(0.f, 0.f, 0.f, 0.f);
                if (gn < N_NODES) v = *(const float4*)(Asrc + (size_t)gn * D + c4);
                uint4 u;
                u.x = f2tf32(v.x); u.y = f2tf32(v.y);
                u.z = f2tf32(v.z); u.w = f2tf32(v.w);
                *(uint4*)&A_s[r + rr][c4] = u;
            }
        }
        // ---- load B tile: 32 k-rows x 128 cols (Ws for k<128, Wn after) ----
        const float* Bsrc = (kc < D) ? (Ws + (size_t)kc * D)
                                     : (Wn + (size_t)(kc - D) * D);
#pragma unroll
        for (int j = 0; j < 4; j++) {
            int idx = tid + j * 256;      // 0..1023
            int row = idx >> 5;           // 0..31
            int c4  = (idx & 31) * 4;     // 0..124
            float4 v = *(const float4*)(Bsrc + (size_t)row * D + c4);
            uint4 u;
            u.x = f2tf32(v.x); u.y = f2tf32(v.y);
            u.z = f2tf32(v.z); u.w = f2tf32(v.w);
            *(uint4*)&B_s[row][c4] = u;
        }
        __syncthreads();

        // ---- compute: 4 k8 steps ----
#pragma unroll
        for (int kk = 0; kk < KC; kk += 8) {
            u32 bf[4][2];
#pragma unroll
            for (int nt = 0; nt < 4; nt++) {
                int col = wn * 32 + nt * 8 + gid;
                bf[nt][0] = B_s[kk + t4][col];
                bf[nt][1] = B_s[kk + t4 + 4][col];
            }
#pragma unroll
            for (int mt = 0; mt < 4; mt++) {
                int row = wm * 64 + mt * 16 + gid;
                u32 a0 = A_s[row][kk + t4];
                u32 a1 = A_s[row + 8][kk + t4];
                u32 a2 = A_s[row][kk + t4 + 4];
                u32 a3 = A_s[row + 8][kk + t4 + 4];
#pragma unroll
                for (int nt = 0; nt < 4; nt++) {
                    asm volatile(
                        "mma.sync.aligned.m16n8k8.row.col.f32.tf32.tf32.f32 "
                        "{%0,%1,%2,%3}, {%4,%5,%6,%7}, {%8,%9}, {%0,%1,%2,%3};"
                        : "+f"(d[mt][nt][0]), "+f"(d[mt][nt][1]),
                          "+f"(d[mt][nt][2]), "+f"(d[mt][nt][3])
                        : "r"(a0), "r"(a1), "r"(a2), "r"(a3),
                          "r"(bf[nt][0]), "r"(bf[nt][1]));
                }
            }
        }
        __syncthreads();
    }

    // ---- epilogue: add bias, store float2 pairs ----
#pragma unroll
    for (int nt = 0; nt < 4; nt++) {
        int col = wn * 32 + nt * 8 + 2 * t4;
        float2 bb = *(const float2*)(bias + col);
#pragma unroll
        for (int mt = 0; mt < 4; mt++) {
            int row = node0 + wm * 64 + mt * 16 + gid;
            if (row < N_NODES) {
                float2 o0; o0.x = d[mt][nt][0] + bb.x; o0.y = d[mt][nt][1] + bb.y;
                *(float2*)(out + (size_t)row * D + col) = o0;
            }
            if (row + 8 < N_NODES) {
                float2 o1; o1.x = d[mt][nt][2] + bb.x; o1.y = d[mt][nt][3] + bb.y;
                *(float2*)(out + (size_t)(row + 8) * D + col) = o1;
            }
        }
    }
}

// ---------------------------------------------------------------------------
// Launch
// ---------------------------------------------------------------------------
extern "C" void kernel_launch(void* const* d_in, const int* in_sizes, int n_in,
                              void* d_out, int out_size) {
    const float* feat  = (const float*)d_in[0];
    const int*   src_w = (const int*)d_in[1];
    const int*   dst_w = (const int*)d_in[2];
    const float* Ws    = (const float*)d_in[3];
    const float* Wn    = (const float*)d_in[4];
    const float* b     = (const float*)d_in[5];
    float*       out   = (float*)d_out;

    zero_probe_kernel<<<(N_NODES + 255) / 256, 256>>>(dst_w);
    count_kernel<<<(N_EDGES + 255) / 256, 256>>>(dst_w);
    scan1_kernel<<<SCAN_BLOCKS, 256>>>();
    scan2_kernel<<<1, 32>>>();
    scan3_kernel<<<SCAN_BLOCKS, 256>>>();
    fill_kernel<<<(N_EDGES + 255) / 256, 256>>>(src_w, dst_w);

    {   // aggregate: one warp per node
        int threads = 256;
        int blocks = (N_NODES * 32 + threads - 1) / threads;
        aggregate_kernel<<<blocks, threads>>>(feat);
    }

    {   // fused dual GEMM on tensor cores
        int blocks = (N_NODES + 127) / 128;   // 391
        gemm_tf32_kernel<<<blocks, 256>>>(feat, Ws, Wn, b, out);
    }
}